// round 12
// baseline (speedup 1.0000x reference)
#include <cuda_runtime.h>
#include <math.h>

#define B_   8
#define T_   256
#define MEL_ 128
#define D_   192
#define NC_  20
#define D2_  384
#define NT_  32
#define ND_  4
#define EPS_ 1e-5f

__device__ float g_xp [B_*T_*D_];
__device__ float g_x2 [B_*T_*D_];
__device__ float g_g2 [B_*T_*D_];
__device__ float g_x3 [B_*T_*D_];
__device__ float g_Kt [B_*NT_*D_];
__device__ float g_Vt [B_*NT_*D_];
__device__ float g_Qt [B_*NT_*D_];
__device__ float g_Fd [B_*ND_*D_];
__device__ float g_al [B_*T_*4];
__device__ float g_Wao [D_*D_];
__device__ float g_bao [D_];
__device__ float g_Wkqd[D_*D_];
__device__ float g_Wkqt[D_*D_];
__device__ float g_pp [B_*16*D_];

__device__ __forceinline__ float cdv(int d) {
    const float L2A = -0.014499569695115089f;   // log2(0.99)
    const float L2E = -0.152003093445049970f;   // log2(0.90)
    float n = (float)(d + 1);
    return (exp2f(n * L2A) - exp2f(n * L2E)) * (0.1f / 0.09f);
}

// ---------------- R3-style tiled GEMM device fn: 64x64 tile, BK=16, 256 threads ----------------
__device__ __forceinline__ void dev_gemm_tile(float* sh,
    const float* __restrict__ A, int ldA, const float* __restrict__ W, int ldW, bool transB,
    const float* __restrict__ bias, const float* __restrict__ res, float* __restrict__ C, int ldC,
    int m0, int n0, int K)
{
    float (*As)[68] = (float (*)[68])sh;
    float (*Ws)[64] = (float (*)[64])(sh + 16 * 68);
    int tid = threadIdx.x;
    int tx = tid & 15, ty = tid >> 4;
    float c[4][4] = {};
    for (int k0 = 0; k0 < K; k0 += 16) {
        {
            int arow = tid >> 2, acol = (tid & 3) * 4;
            float4 v = *(const float4*)&A[(size_t)(m0 + arow) * ldA + k0 + acol];
            As[acol + 0][arow] = v.x; As[acol + 1][arow] = v.y;
            As[acol + 2][arow] = v.z; As[acol + 3][arow] = v.w;
        }
        {
            int wrow = tid >> 4, wcol = (tid & 15) * 4;
            if (transB) {
#pragma unroll
                for (int u = 0; u < 4; u++)
                    Ws[wrow][wcol + u] = W[(size_t)(n0 + wcol + u) * ldW + k0 + wrow];
            } else {
                *(float4*)&Ws[wrow][wcol] = *(const float4*)&W[(size_t)(k0 + wrow) * ldW + n0 + wcol];
            }
        }
        __syncthreads();
#pragma unroll
        for (int kk = 0; kk < 16; kk++) {
            float4 af = *(const float4*)&As[kk][ty * 4];
            float4 bf = *(const float4*)&Ws[kk][tx * 4];
            float a4[4] = {af.x, af.y, af.z, af.w};
            float b4[4] = {bf.x, bf.y, bf.z, bf.w};
#pragma unroll
            for (int i = 0; i < 4; i++)
#pragma unroll
                for (int j = 0; j < 4; j++) c[i][j] = fmaf(a4[i], b4[j], c[i][j]);
        }
        __syncthreads();
    }
#pragma unroll
    for (int i = 0; i < 4; i++) {
        int row = m0 + ty * 4 + i, col = n0 + tx * 4;
        float4 o; float* po = &o.x;
#pragma unroll
        for (int j = 0; j < 4; j++) {
            float v = c[i][j];
            if (bias) v += bias[col + j];
            if (res)  v += res[(size_t)row * ldC + col + j];
            po[j] = v;
        }
        *(float4*)&C[(size_t)row * ldC + col] = o;
    }
}

// ---------------- K1: xp GEMM (96) + Wao (9) + Wkqd (9) + Wkqt (9) + bao (1) ----------------
__global__ void __launch_bounds__(256) k0_comb(
    const float* __restrict__ x, const float* __restrict__ W_in, const float* __restrict__ b_in,
    const float* __restrict__ Wv_a, const float* __restrict__ Wo_a,
    const float* __restrict__ bv_a, const float* __restrict__ bo_a,
    const float* __restrict__ Wk_d, const float* __restrict__ Wq_d,
    const float* __restrict__ Wk_t, const float* __restrict__ Wq_t)
{
    __shared__ __align__(16) float sh[16 * 68 + 16 * 64];
    int blk = blockIdx.x, tid = threadIdx.x;
    if (blk < 96) {
        dev_gemm_tile(sh, x, MEL_, W_in, D_, false, b_in, nullptr, g_xp, D_,
                      (blk / 3) * 64, (blk % 3) * 64, MEL_);
    } else if (blk < 105) {
        int p = blk - 96;
        dev_gemm_tile(sh, Wv_a, D_, Wo_a, D_, false, nullptr, nullptr, g_Wao, D_,
                      (p / 3) * 64, (p % 3) * 64, D_);
    } else if (blk < 114) {
        int p = blk - 105;
        dev_gemm_tile(sh, Wk_d, D_, Wq_d, D_, true, nullptr, nullptr, g_Wkqd, D_,
                      (p / 3) * 64, (p % 3) * 64, D_);
    } else if (blk < 123) {
        int p = blk - 114;
        dev_gemm_tile(sh, Wk_t, D_, Wq_t, D_, true, nullptr, nullptr, g_Wkqt, D_,
                      (p / 3) * 64, (p % 3) * 64, D_);
    } else {
        if (tid < D_) {
            float s = bo_a[tid];
#pragma unroll 8
            for (int e = 0; e < D_; e++) s = fmaf(bv_a[e], Wo_a[e * D_ + tid], s);
            g_bao[tid] = s;
        }
    }
}

// ---------------- K2: full delta-memory chain per batch (grid 8, 256 thr) ----------------
// Produces: F = Ed + Ed@Wao  (global), alpha[t][j] = gated 0.5*cd*(xp_t . Qtilde_j) (global)
__global__ void __launch_bounds__(256) delta_kernel(
    float* __restrict__ alpha_out, float* __restrict__ F_out,
    const float* __restrict__ xp, const float* __restrict__ Wk,
    const float* __restrict__ Wv, const float* __restrict__ Wkq,
    const float* __restrict__ Wao)
{
    __shared__ float sa[ND_][D_];
    __shared__ float sK[ND_][D_ + 1];
    __shared__ float sV[ND_][D_];
    __shared__ float sQ[ND_][D_];
    __shared__ float sE[ND_][D_];
    __shared__ float Acf[ND_][ND_];
    int b = blockIdx.x, tid = threadIdx.x;
    for (int idx = tid; idx < ND_ * D_; idx += 256) {
        int r = idx / D_, c = idx % D_;
        sa[r][c] = xp[(size_t)(b * T_ + r * 64) * D_ + c];
    }
    __syncthreads();
    // projections: K, V, Qtilde (12 rows x 192 cols)
    for (int o = tid; o < 3 * ND_ * D_; o += 256) {
        int m = o / (ND_ * D_);
        int rr = (o / D_) % ND_;
        int c = o % D_;
        const float* W = (m == 0) ? Wk : (m == 1) ? Wv : Wkq;
        float s = 0.f;
#pragma unroll 8
        for (int k = 0; k < D_; k++) s = fmaf(sa[rr][k], W[k * D_ + c], s);
        if (m == 0) sK[rr][c] = s;
        else if (m == 1) sV[rr][c] = s;
        else sQ[rr][c] = s;
    }
    __syncthreads();
    if (tid < 6) {
        const int pi[6] = {1, 2, 2, 3, 3, 3};
        const int pj[6] = {0, 0, 1, 0, 1, 2};
        int i = pi[tid], j = pj[tid];
        float s0 = 0.f, s1 = 0.f;
#pragma unroll 8
        for (int kk = 0; kk < D_; kk += 2) {
            s0 = fmaf(sK[j][kk],     sK[i][kk],     s0);
            s1 = fmaf(sK[j][kk + 1], sK[i][kk + 1], s1);
        }
        Acf[j][i] = cdv(i - 1 - j) * (s0 + s1);
    }
    __syncthreads();
    if (tid < D_) {
        float err[ND_];
#pragma unroll
        for (int i = 0; i < ND_; i++) {
            float s = sV[i][tid];
#pragma unroll
            for (int j = 0; j < i; j++) s -= Acf[j][i] * err[j];
            err[i] = s;
            sE[i][tid] = s;
        }
    }
    __syncthreads();
    // F = Ed + Ed @ Wao
    for (int o = tid; o < ND_ * D_; o += 256) {
        int rr = o / D_, c = o % D_;
        float s = sE[rr][c];
#pragma unroll 8
        for (int k = 0; k < D_; k++) s = fmaf(sE[rr][k], Wao[k * D_ + c], s);
        F_out[(size_t)(b * ND_ + rr) * D_ + c] = s;
    }
    // alpha: one t per thread, float4 loads for MLP
    {
        int t = tid;
        const float4* xr = (const float4*)&xp[(size_t)(b * T_ + t) * D_];
        float a0 = 0.f, a1 = 0.f, a2 = 0.f, a3 = 0.f;
#pragma unroll 8
        for (int k4 = 0; k4 < 48; k4++) {
            float4 v = xr[k4];
            int k = k4 * 4;
            a0 = fmaf(v.x, sQ[0][k+0], a0); a0 = fmaf(v.y, sQ[0][k+1], a0);
            a0 = fmaf(v.z, sQ[0][k+2], a0); a0 = fmaf(v.w, sQ[0][k+3], a0);
            a1 = fmaf(v.x, sQ[1][k+0], a1); a1 = fmaf(v.y, sQ[1][k+1], a1);
            a1 = fmaf(v.z, sQ[1][k+2], a1); a1 = fmaf(v.w, sQ[1][k+3], a1);
            a2 = fmaf(v.x, sQ[2][k+0], a2); a2 = fmaf(v.y, sQ[2][k+1], a2);
            a2 = fmaf(v.z, sQ[2][k+2], a2); a2 = fmaf(v.w, sQ[2][k+3], a2);
            a3 = fmaf(v.x, sQ[3][k+0], a3); a3 = fmaf(v.y, sQ[3][k+1], a3);
            a3 = fmaf(v.z, sQ[3][k+2], a3); a3 = fmaf(v.w, sQ[3][k+3], a3);
        }
        int r = t >> 6;
        float4 al;
        al.x = 0.5f * cdv(r) * a0;
        al.y = (1 <= r) ? 0.5f * cdv(r - 1) * a1 : 0.f;
        al.z = (2 <= r) ? 0.5f * cdv(r - 2) * a2 : 0.f;
        al.w = (3 <= r) ? 0.5f * cdv(r - 3) * a3 : 0.f;
        *(float4*)&alpha_out[(size_t)(b * T_ + t) * 4] = al;
    }
}

// ---------------- K3: x2 = xp + xp@Wao + bao + alpha@F  (grid 96) ----------------
__global__ void __launch_bounds__(256) x2_lite(
    float* __restrict__ x2, const float* __restrict__ xp,
    const float* __restrict__ Wao, const float* __restrict__ bao,
    const float* __restrict__ alpha, const float* __restrict__ Fd)
{
    __shared__ __align__(16) float sh[16 * 68 + 16 * 64];
    __shared__ __align__(16) float sF[ND_][D_];
    __shared__ float salph[64][4];
    int blk = blockIdx.x;
    int m0 = (blk / 3) * 64, n0 = (blk % 3) * 64;
    int b = m0 >> 8;
    int tid = threadIdx.x;
    for (int idx = tid; idx < ND_ * D_; idx += 256)
        sF[idx / D_][idx % D_] = Fd[(size_t)b * ND_ * D_ + idx];
    if (tid < 64)
        *(float4*)&salph[tid][0] = *(const float4*)&alpha[(size_t)(m0 + tid) * 4];
    // GEMM core (includes its own syncthreads before first use of sh)
    float (*As)[68] = (float (*)[68])sh;
    float (*Ws)[64] = (float (*)[64])(sh + 16 * 68);
    int tx = tid & 15, ty = tid >> 4;
    float c[4][4] = {};
    for (int k0 = 0; k0 < D_; k0 += 16) {
        {
            int arow = tid >> 2, acol = (tid & 3) * 4;
            float4 v = *(const float4*)&xp[(size_t)(m0 + arow) * D_ + k0 + acol];
            As[acol + 0][arow] = v.x; As[acol + 1][arow] = v.y;
            As[acol + 2][arow] = v.z; As[acol + 3][arow] = v.w;
        }
        {
            int wrow = tid >> 4, wcol = (tid & 15) * 4;
            *(float4*)&Ws[wrow][wcol] = *(const float4*)&Wao[(size_t)(k0 + wrow) * D_ + n0 + wcol];
        }
        __syncthreads();
#pragma unroll
        for (int kk = 0; kk < 16; kk++) {
            float4 af = *(const float4*)&As[kk][ty * 4];
            float4 bf = *(const float4*)&Ws[kk][tx * 4];
            float a4[4] = {af.x, af.y, af.z, af.w};
            float b4[4] = {bf.x, bf.y, bf.z, bf.w};
#pragma unroll
            for (int i = 0; i < 4; i++)
#pragma unroll
                for (int j = 0; j < 4; j++) c[i][j] = fmaf(a4[i], b4[j], c[i][j]);
        }
        __syncthreads();
    }
#pragma unroll
    for (int i = 0; i < 4; i++) {
        int lrow = ty * 4 + i, row = m0 + lrow, col = n0 + tx * 4;
        float4 rv = *(const float4*)&xp[(size_t)row * D_ + col];
        float4 o; float* po = &o.x;
        const float* prv = &rv.x;
#pragma unroll
        for (int j = 0; j < 4; j++) {
            float v = c[i][j] + bao[col + j] + prv[j];
#pragma unroll
            for (int jj = 0; jj < ND_; jj++)
                v = fmaf(salph[lrow][jj], sF[jj][col + j], v);
            po[j] = v;
        }
        *(float4*)&x2[(size_t)row * D_ + col] = o;
    }
}

// ---------------- K4: glu_ln = LN1 in smem + GLU GEMM (grid 96, dyn smem) ----------------
__global__ void __launch_bounds__(256) glu_ln(
    const float* __restrict__ x2, const float* __restrict__ g1, const float* __restrict__ b1,
    const float* __restrict__ W, const float* __restrict__ bias,
    const float* __restrict__ dw, const float* __restrict__ db,
    const float* __restrict__ bs, const float* __restrict__ bb, float* __restrict__ outp)
{
    extern __shared__ __align__(16) float sh[];
    float (*Xs)[68] = (float (*)[68])sh;       // [192][68]
    float* Wa = sh + 192 * 68;                  // [16][64]
    float* Wg = Wa + 16 * 64;
    float* rowm = Wg + 16 * 64;                 // [64]
    float* rowr = rowm + 64;
    int blk = blockIdx.x;
    int m0 = (blk / 3) * 64, n0 = (blk % 3) * 64;
    int tid = threadIdx.x, tx = tid & 15, ty = tid >> 4;
    for (int k0 = 0; k0 < D_; k0 += 16) {
        int arow = tid >> 2, acol = (tid & 3) * 4;
        float4 v = *(const float4*)&x2[(size_t)(m0 + arow) * D_ + k0 + acol];
        Xs[k0 + acol + 0][arow] = v.x; Xs[k0 + acol + 1][arow] = v.y;
        Xs[k0 + acol + 2][arow] = v.z; Xs[k0 + acol + 3][arow] = v.w;
    }
    __syncthreads();
    if (tid < 64) {
        float s = 0.f, s2 = 0.f;
#pragma unroll 8
        for (int k = 0; k < D_; k++) { float v = Xs[k][tid]; s += v; s2 += v * v; }
        float m = s / D_;
        rowm[tid] = m;
        rowr[tid] = rsqrtf(s2 / D_ - m * m + EPS_);
    }
    __syncthreads();
    for (int idx = tid; idx < D_ * 64; idx += 256) {
        int k = idx >> 6, r = idx & 63;
        Xs[k][r] = (Xs[k][r] - rowm[r]) * rowr[r] * g1[k] + b1[k];
    }
    __syncthreads();
    float cA[4][4] = {}, cG[4][4] = {};
    for (int k0 = 0; k0 < D_; k0 += 16) {
        {
            int wrow = tid >> 4, wcol = (tid & 15) * 4;
            *(float4*)&Wa[wrow * 64 + wcol] = *(const float4*)&W[(size_t)(k0 + wrow) * D2_ + n0 + wcol];
            *(float4*)&Wg[wrow * 64 + wcol] = *(const float4*)&W[(size_t)(k0 + wrow) * D2_ + D_ + n0 + wcol];
        }
        __syncthreads();
#pragma unroll
        for (int kk = 0; kk < 16; kk++) {
            float4 af = *(const float4*)&Xs[k0 + kk][ty * 4];
            float4 ba = *(const float4*)&Wa[kk * 64 + tx * 4];
            float4 bg = *(const float4*)&Wg[kk * 64 + tx * 4];
            float a4[4] = {af.x, af.y, af.z, af.w};
            float p4[4] = {ba.x, ba.y, ba.z, ba.w};
            float q4[4] = {bg.x, bg.y, bg.z, bg.w};
#pragma unroll
            for (int i = 0; i < 4; i++)
#pragma unroll
                for (int j = 0; j < 4; j++) {
                    cA[i][j] = fmaf(a4[i], p4[j], cA[i][j]);
                    cG[i][j] = fmaf(a4[i], q4[j], cG[i][j]);
                }
        }
        __syncthreads();
    }
#pragma unroll
    for (int i = 0; i < 4; i++) {
        int row = m0 + ty * 4 + i, col = n0 + tx * 4;
        float4 o; float* po = &o.x;
#pragma unroll
        for (int j = 0; j < 4; j++) {
            float a = cA[i][j] + bias[col + j];
            float g = cG[i][j] + bias[D_ + col + j];
            float h = a * (1.f / (1.f + expf(-g)));
            h = h * dw[col + j] + db[col + j];
            h = h * bs[col + j] + bb[col + j];
            h = h * (1.f / (1.f + expf(-h)));
            po[j] = h;
        }
        *(float4*)&outp[(size_t)row * D_ + col] = o;
    }
}

// ---------------- K5: pw2 GEMM with residual (grid 96) ----------------
__global__ void __launch_bounds__(256) gemm_pw2(
    float* __restrict__ C, const float* __restrict__ A, const float* __restrict__ W,
    const float* __restrict__ bias, const float* __restrict__ res)
{
    __shared__ __align__(16) float sh[16 * 68 + 16 * 64];
    dev_gemm_tile(sh, A, D_, W, D_, false, bias, res, C, D_,
                  (blockIdx.x / 3) * 64, (blockIdx.x % 3) * 64, D_);
}

// ---------------- K6: theta K/V/Ktilde (grid 256) ----------------
__global__ void __launch_bounds__(192) projKVQ(
    float* __restrict__ Ko, float* __restrict__ Vo, float* __restrict__ Qo,
    const float* __restrict__ A, const float* __restrict__ Wk,
    const float* __restrict__ Wv, const float* __restrict__ Wkq, int nUpd, int chunk)
{
    __shared__ float sa[D_];
    int blk = blockIdx.x;
    int b = blk / nUpd, i = blk % nUpd;
    int tid = threadIdx.x;
    sa[tid] = A[(size_t)(b * T_ + i * chunk) * D_ + tid];
    __syncthreads();
    if (tid < 144) {
        int gsel = tid / 48, q = tid % 48;
        const float* W = (gsel == 0) ? Wk : (gsel == 1) ? Wv : Wkq;
        float ax = 0.f, ay = 0.f, az = 0.f, aw = 0.f;
#pragma unroll 16
        for (int kk = 0; kk < D_; kk++) {
            float a = sa[kk];
            float4 w = *(const float4*)&W[kk * D_ + 4 * q];
            ax = fmaf(a, w.x, ax); ay = fmaf(a, w.y, ay);
            az = fmaf(a, w.z, az); aw = fmaf(a, w.w, aw);
        }
        float* O = (gsel == 0) ? Ko : (gsel == 1) ? Vo : Qo;
        float4 o = {ax, ay, az, aw};
        *(float4*)&O[(size_t)blk * D_ + 4 * q] = o;
    }
}

// ---------------- K7: qkfinal with in-block theta err recurrence (grid 128, dyn smem) ----------------
__global__ void __launch_bounds__(192) qkfinal_rec(
    const float* __restrict__ x3, const float* __restrict__ Kt, const float* __restrict__ Ktil,
    const float* __restrict__ Vt,
    const float* __restrict__ g2, const float* __restrict__ b2, float* __restrict__ pp)
{
    extern __shared__ __align__(16) float sh[];
    float (*sKT)[33] = (float (*)[33])sh;      // Ktil transposed [192][33] (for q-dots)
    float (*sKG)[33] = (float (*)[33])(sh + 192 * 33); // Kt transposed (for Gram)
    float* sEt = sh + 2 * 192 * 33;            // [32][192]
    float* Acf = sEt + NT_ * D_;               // [32][32]
    float* red = Acf + NT_ * NT_;              // [32][6]
    float* alpha = red + 192;
    float* cd = alpha + 32;
    float* lred = cd + 32;                     // [12]
    int blk = blockIdx.x;
    int b = blk >> 4, tc = blk & 15, t0 = tc * 16;
    int tid = threadIdx.x;
    if (tid < NT_) cd[tid] = cdv(tid);
    for (int idx = tid; idx < NT_ * D_; idx += 192) {
        int j = idx / D_, e = idx % D_;
        sKT[e][j] = Ktil[(size_t)(b * NT_ + j) * D_ + e];
        sKG[e][j] = Kt[(size_t)(b * NT_ + j) * D_ + e];
    }
    __syncthreads();
    // Gram coefficients (496 pairs over 192 threads)
    const int NP = NT_ * (NT_ - 1) / 2;
    for (int p = tid; p < NP; p += 192) {
        int i = (int)((1.0f + sqrtf(1.0f + 8.0f * (float)p)) * 0.5f);
        while (i * (i - 1) / 2 > p) i--;
        while ((i + 1) * i / 2 <= p) i++;
        int j = p - i * (i - 1) / 2;
        float s0 = 0.f, s1 = 0.f;
#pragma unroll 8
        for (int e = 0; e < D_; e += 2) {
            s0 = fmaf(sKG[e][j],     sKG[e][i],     s0);
            s1 = fmaf(sKG[e + 1][j], sKG[e + 1][i], s1);
        }
        Acf[j * NT_ + i] = cd[i - 1 - j] * (s0 + s1);
    }
    __syncthreads();
    // err chain
    {
        int e = tid;
        float err[NT_];
#pragma unroll
        for (int i = 0; i < NT_; i++) {
            float a0 = 0.f, a1 = 0.f;
#pragma unroll
            for (int j = 0; j < i; j++) {
                if (j & 1) a1 = fmaf(Acf[j * NT_ + i], err[j], a1);
                else       a0 = fmaf(Acf[j * NT_ + i], err[j], a0);
            }
            err[i] = Vt[(size_t)(b * NT_ + i) * D_ + e] - a0 - a1;
            sEt[i * D_ + e] = err[i];
        }
    }
    __syncthreads();
    int j = tid & 31, g = tid >> 5;
    float ps = 0.f;
    for (int tt = 0; tt < 16; tt++) {
        int t = t0 + tt, row = b * T_ + t, r = t >> 3;
        {
            const float* qr = x3 + (size_t)row * D_;
            float part = 0.f;
#pragma unroll
            for (int u = 0; u < 32; u++) part = fmaf(qr[g * 32 + u], sKT[g * 32 + u][j], part);
            red[j * 6 + g] = part;
        }
        __syncthreads();
        if (tid < NT_) {
            float s = 0.f;
#pragma unroll
            for (int gg = 0; gg < 6; gg++) s += red[tid * 6 + gg];
            alpha[tid] = (tid <= r) ? cd[r - tid] * s : 0.f;
        }
        __syncthreads();
        float s = 0.f;
        for (int jj = 0; jj <= r; jj++) s = fmaf(alpha[jj], sEt[jj * D_ + tid], s);
        float x4 = x3[(size_t)row * D_ + tid] + 0.5f * s;
        float sm = x4, s2 = x4 * x4;
#pragma unroll
        for (int o = 16; o > 0; o >>= 1) {
            sm += __shfl_xor_sync(~0u, sm, o);
            s2 += __shfl_xor_sync(~0u, s2, o);
        }
        if ((tid & 31) == 0) { lred[tid >> 5] = sm; lred[6 + (tid >> 5)] = s2; }
        __syncthreads();
        float ts = 0.f, ts2 = 0.f;
#pragma unroll
        for (int i = 0; i < 6; i++) { ts += lred[i]; ts2 += lred[6 + i]; }
        float m = ts / D_;
        float var = ts2 / D_ - m * m;
        ps += (x4 - m) * rsqrtf(var + EPS_) * g2[tid] + b2[tid];
        __syncthreads();
    }
    pp[(size_t)(b * 16 + tc) * D_ + tid] = ps;
}

// ---------------- K8: pool + classifier ----------------
__global__ void __launch_bounds__(192) poolcls(
    const float* __restrict__ pp, const float* __restrict__ Wc,
    const float* __restrict__ bc, float* __restrict__ out)
{
    __shared__ float pooled[D_];
    int b = blockIdx.x, tid = threadIdx.x;
    float s = 0.f;
#pragma unroll
    for (int q = 0; q < 16; q++) s += pp[(size_t)(b * 16 + q) * D_ + tid];
    pooled[tid] = s * (1.f / T_);
    __syncthreads();
    if (tid < NC_) {
        float acc = bc[tid];
#pragma unroll 8
        for (int e = 0; e < D_; e++) acc = fmaf(pooled[e], Wc[e * NC_ + tid], acc);
        out[b * NC_ + tid] = acc;
    }
}

// =====================================================================
extern "C" void kernel_launch(void* const* d_in, const int* in_sizes, int n_in,
                              void* d_out, int out_size)
{
    const float* x     = (const float*)d_in[0];
    const float* W_in  = (const float*)d_in[1];
    const float* b_in  = (const float*)d_in[2];
    const float* Wv_a  = (const float*)d_in[3];
    const float* bv_a  = (const float*)d_in[4];
    const float* Wo_a  = (const float*)d_in[5];
    const float* bo_a  = (const float*)d_in[6];
    const float* ln1_g = (const float*)d_in[7];
    const float* ln1_b = (const float*)d_in[8];
    const float* pw1_w = (const float*)d_in[9];
    const float* pw1_b = (const float*)d_in[10];
    const float* dw_w  = (const float*)d_in[11];
    const float* dw_b  = (const float*)d_in[12];
    const float* bn_s  = (const float*)d_in[13];
    const float* bn_b  = (const float*)d_in[14];
    const float* pw2_w = (const float*)d_in[15];
    const float* pw2_b = (const float*)d_in[16];
    const float* Wk_t  = (const float*)d_in[17];
    const float* Wv_t  = (const float*)d_in[18];
    const float* Wq_t  = (const float*)d_in[19];
    const float* Wk_d  = (const float*)d_in[20];
    const float* Wv_d  = (const float*)d_in[21];
    const float* Wq_d  = (const float*)d_in[22];
    const float* ln2_g = (const float*)d_in[23];
    const float* ln2_b = (const float*)d_in[24];
    const float* Wc    = (const float*)d_in[25];
    const float* bc    = (const float*)d_in[26];
    float* out = (float*)d_out;

    float *xp, *x2, *g2p, *x3, *Kt, *Vt, *Qt, *Fd, *al;
    float *Wao, *bao, *Wkqd, *Wkqt, *pp;
    cudaGetSymbolAddress((void**)&xp,   g_xp);
    cudaGetSymbolAddress((void**)&x2,   g_x2);
    cudaGetSymbolAddress((void**)&g2p,  g_g2);
    cudaGetSymbolAddress((void**)&x3,   g_x3);
    cudaGetSymbolAddress((void**)&Kt,   g_Kt);
    cudaGetSymbolAddress((void**)&Vt,   g_Vt);
    cudaGetSymbolAddress((void**)&Qt,   g_Qt);
    cudaGetSymbolAddress((void**)&Fd,   g_Fd);
    cudaGetSymbolAddress((void**)&al,   g_al);
    cudaGetSymbolAddress((void**)&Wao,  g_Wao);
    cudaGetSymbolAddress((void**)&bao,  g_bao);
    cudaGetSymbolAddress((void**)&Wkqd, g_Wkqd);
    cudaGetSymbolAddress((void**)&Wkqt, g_Wkqt);
    cudaGetSymbolAddress((void**)&pp,   g_pp);

    const int GLU_SMEM  = (192 * 68 + 2 * 16 * 64 + 128) * 4;
    const int QKFR_SMEM = (2 * 192 * 33 + NT_ * D_ + NT_ * NT_ + 192 + 32 + 32 + 12) * 4;
    cudaFuncSetAttribute(glu_ln,      cudaFuncAttributeMaxDynamicSharedMemorySize, GLU_SMEM);
    cudaFuncSetAttribute(qkfinal_rec, cudaFuncAttributeMaxDynamicSharedMemorySize, QKFR_SMEM);

    // 1) xp GEMM + weight folds
    k0_comb<<<124, 256>>>(x, W_in, b_in, Wv_a, Wo_a, bv_a, bo_a,
                          Wk_d, Wq_d, Wk_t, Wq_t);
    // 2) delta chain: K/V/Qtilde + err + F + alpha  (one launch)
    delta_kernel<<<B_, 256>>>(al, Fd, xp, Wk_d, Wv_d, Wkqd, Wao);
    // 3) x2 = xp + xp@Wao + bao + alpha@F
    x2_lite<<<96, 256>>>(x2, xp, Wao, bao, al, Fd);
    // 4) LN1 + GLU GEMM
    glu_ln<<<96, 256, GLU_SMEM>>>(x2, ln1_g, ln1_b, pw1_w, pw1_b, dw_w, dw_b, bn_s, bn_b, g2p);
    // 5) x3 = x2 + g2@pw2 + b
    gemm_pw2<<<96, 256>>>(x3, g2p, pw2_w, pw2_b, x2);
    // 6) theta K/V/Ktilde
    projKVQ<<<B_ * NT_, 192>>>(Kt, Vt, Qt, x3, Wk_t, Wv_t, Wkqt, NT_, 8);
    // 7) theta err (in-block) + retrieval + LN2 -> partial pools
    qkfinal_rec<<<B_ * 16, 192, QKFR_SMEM>>>(x3, Kt, Qt, Vt, ln2_g, ln2_b, pp);
    // 8) pool + classifier
    poolcls<<<B_, 192>>>(pp, Wc, bc, out);
}

// round 13
// speedup vs baseline: 1.3016x; 1.3016x over previous
#include <cuda_runtime.h>
#include <math.h>

#define B_   8
#define T_   256
#define MEL_ 128
#define D_   192
#define NC_  20
#define D2_  384
#define NT_  32
#define ND_  4
#define EPS_ 1e-5f

__device__ float g_xp [B_*T_*D_];
__device__ float g_x2 [B_*T_*D_];
__device__ float g_g2 [B_*T_*D_];
__device__ float g_x3 [B_*T_*D_];
__device__ float g_Kd [B_*ND_*D_];
__device__ float g_Vd [B_*ND_*D_];
__device__ float g_Qd [B_*ND_*D_];
__device__ float g_Ed [B_*ND_*D_];
__device__ float g_Fd [B_*ND_*D_];
__device__ float g_Kt [B_*NT_*D_];
__device__ float g_Vt [B_*NT_*D_];
__device__ float g_Qt [B_*NT_*D_];
__device__ float g_Et [B_*NT_*D_];
__device__ float g_Wao [D_*D_];
__device__ float g_bao [D_];
__device__ float g_Wkqd[D_*D_];
__device__ float g_Wkqt[D_*D_];
__device__ float g_pp [B_*16*D_];

__device__ __forceinline__ float cdv(int d) {
    const float L2A = -0.014499569695115089f;   // log2(0.99)
    const float L2E = -0.152003093445049970f;   // log2(0.90)
    float n = (float)(d + 1);
    return (exp2f(n * L2A) - exp2f(n * L2E)) * (0.1f / 0.09f);
}

// ============ split-K full-K-resident GEMM pieces: 512 threads, 64x64 tile ============
// Asf[k*68 + row] (A transposed, padded stride 68), Wsf[k*64 + col]
// kh = tid>>8 selects k-half; sub = tid&255 maps a 16x16 thread grid, 4x4 outputs each.
#define AST 68
#define ASF_FLOATS (192 * AST)
#define WSF_FLOATS (192 * 64)
#define GEMM_SMEM  ((ASF_FLOATS + WSF_FLOATS) * 4)

__device__ __forceinline__ void skA(float* Asf, const float* __restrict__ A,
                                    int ldA, int m0, int K)
{
    int tid = threadIdx.x;
    int kq = K >> 2;
    for (int idx = tid; idx < 64 * kq; idx += 512) {
        int r = idx / kq, c4 = idx - r * kq;
        float4 v = *(const float4*)&A[(size_t)(m0 + r) * ldA + c4 * 4];
        Asf[(c4 * 4 + 0) * AST + r] = v.x;
        Asf[(c4 * 4 + 1) * AST + r] = v.y;
        Asf[(c4 * 4 + 2) * AST + r] = v.z;
        Asf[(c4 * 4 + 3) * AST + r] = v.w;
    }
}
__device__ __forceinline__ void skW(float* Wsf, const float* __restrict__ W,
                                    int ldW, int n0, int K, bool transB)
{
    int tid = threadIdx.x;
    if (transB) {
        for (int idx = tid; idx < K * 64; idx += 512) {
            int k = idx >> 6, cc = idx & 63;
            Wsf[k * 64 + cc] = W[(size_t)(n0 + cc) * ldW + k];
        }
    } else {
        for (int idx = tid; idx < K * 16; idx += 512) {
            int k = idx >> 4, c4 = idx & 15;
            *(float4*)&Wsf[k * 64 + c4 * 4] =
                *(const float4*)&W[(size_t)k * ldW + n0 + c4 * 4];
        }
    }
}
template<int K>
__device__ __forceinline__ void skC(const float* Asf, const float* Wsf,
                                    float c[4][4], int kh, int sub)
{
    int tx = sub & 15, ty = sub >> 4;
    const float* pa = Asf + kh * (K / 2) * AST + ty * 4;
    const float* pb = Wsf + kh * (K / 2) * 64 + tx * 4;
#pragma unroll 8
    for (int kk = 0; kk < K / 2; kk++) {
        float4 af = *(const float4*)(pa + kk * AST);
        float4 bf = *(const float4*)(pb + kk * 64);
        float a4[4] = {af.x, af.y, af.z, af.w};
        float b4[4] = {bf.x, bf.y, bf.z, bf.w};
#pragma unroll
        for (int i = 0; i < 4; i++)
#pragma unroll
            for (int j = 0; j < 4; j++) c[i][j] = fmaf(a4[i], b4[j], c[i][j]);
    }
}
// combine halves: kh=1 stores into red (16KB, typically aliasing dead Wsf), kh=0 adds
__device__ __forceinline__ void skReduce(float* red, float c[4][4], int kh, int sub)
{
    int tx = sub & 15, ty = sub >> 4;
    __syncthreads();
    if (kh == 1) {
#pragma unroll
        for (int i = 0; i < 4; i++) {
            float4 o = {c[i][0], c[i][1], c[i][2], c[i][3]};
            *(float4*)&red[(ty * 4 + i) * 64 + tx * 4] = o;
        }
    }
    __syncthreads();
    if (kh == 0) {
#pragma unroll
        for (int i = 0; i < 4; i++) {
            float4 v = *(const float4*)&red[(ty * 4 + i) * 64 + tx * 4];
            c[i][0] += v.x; c[i][1] += v.y; c[i][2] += v.z; c[i][3] += v.w;
        }
    }
}

// ---------------- K1: xp GEMM (96) + Wao (9) + Wkqd (9) + Wkqt (9) + bao (1) ----------------
__global__ void __launch_bounds__(512) k0_comb(
    const float* __restrict__ x, const float* __restrict__ W_in, const float* __restrict__ b_in,
    const float* __restrict__ Wv_a, const float* __restrict__ Wo_a,
    const float* __restrict__ bv_a, const float* __restrict__ bo_a,
    const float* __restrict__ Wk_d, const float* __restrict__ Wq_d,
    const float* __restrict__ Wk_t, const float* __restrict__ Wq_t)
{
    extern __shared__ __align__(16) float sh[];
    float* Asf = sh;
    float* Wsf = sh + ASF_FLOATS;
    int blk = blockIdx.x, tid = threadIdx.x;
    int kh = tid >> 8, sub = tid & 255;

    const float* A; const float* W; const float* bias = nullptr; float* C;
    int ldA, ldW, m0, n0, K; bool transB = false;
    if (blk < 96) {
        A = x; ldA = MEL_; W = W_in; ldW = D_; bias = b_in; C = g_xp;
        m0 = (blk / 3) * 64; n0 = (blk % 3) * 64; K = MEL_;
    } else if (blk < 105) {
        int p = blk - 96;
        A = Wv_a; ldA = D_; W = Wo_a; ldW = D_; C = g_Wao;
        m0 = (p / 3) * 64; n0 = (p % 3) * 64; K = D_;
    } else if (blk < 114) {
        int p = blk - 105;
        A = Wk_d; ldA = D_; W = Wq_d; ldW = D_; C = g_Wkqd; transB = true;
        m0 = (p / 3) * 64; n0 = (p % 3) * 64; K = D_;
    } else if (blk < 123) {
        int p = blk - 114;
        A = Wk_t; ldA = D_; W = Wq_t; ldW = D_; C = g_Wkqt; transB = true;
        m0 = (p / 3) * 64; n0 = (p % 3) * 64; K = D_;
    } else {
        if (tid < D_) {
            float s = bo_a[tid];
#pragma unroll 8
            for (int e = 0; e < D_; e++) s = fmaf(bv_a[e], Wo_a[e * D_ + tid], s);
            g_bao[tid] = s;
        }
        return;
    }
    skA(Asf, A, ldA, m0, K);
    skW(Wsf, W, ldW, n0, K, transB);
    __syncthreads();
    float c[4][4] = {};
    if (K == MEL_) skC<MEL_>(Asf, Wsf, c, kh, sub);
    else           skC<D_>(Asf, Wsf, c, kh, sub);
    skReduce(Wsf, c, kh, sub);
    if (kh == 0) {
        int tx = sub & 15, ty = sub >> 4;
#pragma unroll
        for (int i = 0; i < 4; i++) {
            int row = m0 + ty * 4 + i, col = n0 + tx * 4;
            float4 o; float* po = &o.x;
#pragma unroll
            for (int j = 0; j < 4; j++) {
                float v = c[i][j];
                if (bias) v += bias[col + j];
                po[j] = v;
            }
            *(float4*)&C[(size_t)row * D_ + col] = o;
        }
    }
}

// ---------------- projKVQ ----------------
__global__ void __launch_bounds__(192) projKVQ(
    float* __restrict__ Ko, float* __restrict__ Vo, float* __restrict__ Qo,
    const float* __restrict__ A, const float* __restrict__ Wk,
    const float* __restrict__ Wv, const float* __restrict__ Wkq, int nUpd, int chunk)
{
    __shared__ float sa[D_];
    int blk = blockIdx.x;
    int b = blk / nUpd, i = blk % nUpd;
    int tid = threadIdx.x;
    sa[tid] = A[(size_t)(b * T_ + i * chunk) * D_ + tid];
    __syncthreads();
    if (tid < 144) {
        int gsel = tid / 48, q = tid % 48;
        const float* W = (gsel == 0) ? Wk : (gsel == 1) ? Wv : Wkq;
        float ax = 0.f, ay = 0.f, az = 0.f, aw = 0.f;
#pragma unroll 16
        for (int kk = 0; kk < D_; kk++) {
            float a = sa[kk];
            float4 w = *(const float4*)&W[kk * D_ + 4 * q];
            ax = fmaf(a, w.x, ax); ay = fmaf(a, w.y, ay);
            az = fmaf(a, w.z, az); aw = fmaf(a, w.w, aw);
        }
        float* O = (gsel == 0) ? Ko : (gsel == 1) ? Vo : Qo;
        float4 o = {ax, ay, az, aw};
        *(float4*)&O[(size_t)blk * D_ + 4 * q] = o;
    }
}

// ---------------- rec_d (+F fold) ----------------
__global__ void __launch_bounds__(256) rec_d_kernel(
    float* __restrict__ ERR, float* __restrict__ F,
    const float* __restrict__ Kmat, const float* __restrict__ Vmat,
    const float* __restrict__ Wao)
{
    __shared__ float sK[ND_][D_ + 1];
    __shared__ float sE[ND_][D_];
    __shared__ float Acf[ND_][ND_];
    int b = blockIdx.x, tid = threadIdx.x;
    for (int idx = tid; idx < ND_ * D_; idx += 256)
        sK[idx / D_][idx % D_] = Kmat[(size_t)b * ND_ * D_ + idx];
    __syncthreads();
    if (tid < 6) {
        const int pi[6] = {1, 2, 2, 3, 3, 3};
        const int pj[6] = {0, 0, 1, 0, 1, 2};
        int i = pi[tid], j = pj[tid];
        float s0 = 0.f, s1 = 0.f;
#pragma unroll 8
        for (int kk = 0; kk < D_; kk += 2) {
            s0 = fmaf(sK[j][kk],     sK[i][kk],     s0);
            s1 = fmaf(sK[j][kk + 1], sK[i][kk + 1], s1);
        }
        Acf[j][i] = cdv(i - 1 - j) * (s0 + s1);
    }
    __syncthreads();
    if (tid < D_) {
        float err[ND_];
#pragma unroll
        for (int i = 0; i < ND_; i++) {
            float s = Vmat[(size_t)(b * ND_ + i) * D_ + tid];
#pragma unroll
            for (int j = 0; j < i; j++) s -= Acf[j][i] * err[j];
            err[i] = s;
            sE[i][tid] = s;
            ERR[(size_t)(b * ND_ + i) * D_ + tid] = s;
        }
    }
    __syncthreads();
    if (tid < 192) {
        int j = tid / 48, q = tid % 48;
        float4 acc = *(float4*)&sE[j][4 * q];
#pragma unroll 8
        for (int e = 0; e < D_; e++) {
            float a = sE[j][e];
            float4 w = *(const float4*)&Wao[e * D_ + 4 * q];
            acc.x = fmaf(a, w.x, acc.x); acc.y = fmaf(a, w.y, acc.y);
            acc.z = fmaf(a, w.z, acc.z); acc.w = fmaf(a, w.w, acc.w);
        }
        *(float4*)&F[(size_t)(b * ND_ + j) * D_ + 4 * q] = acc;
    }
}

// ---------------- x2 fused: x2 = xp + xp@Wao + bao + alpha@F (split-K 512) ----------------
__global__ void __launch_bounds__(512) x2_fused(
    const float* __restrict__ xp, const float* __restrict__ Wao, const float* __restrict__ bao,
    const float* __restrict__ Qd, const float* __restrict__ Fd, float* __restrict__ x2)
{
    extern __shared__ __align__(16) float sh[];
    float* Asf = sh;                       // xp tile transposed [192][68]
    float* Wsf = sh + ASF_FLOATS;          // Wao [192][64]; later red
    float* sQ  = Wsf + WSF_FLOATS;         // [4*192]
    float* sF  = sQ + ND_ * D_;            // [4*192]
    float* alph = sF + ND_ * D_;           // [64][4]
    int blk = blockIdx.x;
    int m0 = (blk / 3) * 64, n0 = (blk % 3) * 64;
    int b = m0 >> 8;
    int tid = threadIdx.x;
    int kh = tid >> 8, sub = tid & 255;

    skA(Asf, xp, D_, m0, D_);
    skW(Wsf, Wao, D_, n0, D_, false);
    for (int idx = tid; idx < ND_ * D_; idx += 512) {
        sQ[idx] = Qd[(size_t)b * ND_ * D_ + idx];
        sF[idx] = Fd[(size_t)b * ND_ * D_ + idx];
    }
    __syncthreads();
    float c[4][4] = {};
    skC<D_>(Asf, Wsf, c, kh, sub);
    // alpha: 512 threads = 64 rows x 4 j x 2 halves, from smem xp tile
    {
        int row = tid >> 3, j = (tid >> 1) & 3, half = tid & 1;
        const float* qj = &sQ[j * D_ + half * 96];
        const float* ar = Asf + half * 96 * AST + row;
        float s0 = 0.f, s1 = 0.f;
#pragma unroll 12
        for (int k = 0; k < 96; k += 2) {
            s0 = fmaf(ar[(k + 0) * AST], qj[k + 0], s0);
            s1 = fmaf(ar[(k + 1) * AST], qj[k + 1], s1);
        }
        float s = s0 + s1;
        s += __shfl_xor_sync(~0u, s, 1);
        if (half == 0) {
            int t = (m0 + row) & (T_ - 1), r = t >> 6;
            alph[row * 4 + j] = (j <= r) ? 0.5f * cdv(r - j) * s : 0.f;
        }
    }
    skReduce(Wsf, c, kh, sub);   // syncs also publish alph
    if (kh == 0) {
        int tx = sub & 15, ty = sub >> 4;
#pragma unroll
        for (int i = 0; i < 4; i++) {
            int lrow = ty * 4 + i, row = m0 + lrow, col = n0 + tx * 4;
            float4 o; float* po = &o.x;
#pragma unroll
            for (int j = 0; j < 4; j++) {
                float v = c[i][j] + bao[col + j] + Asf[(col + j) * AST + lrow];
#pragma unroll
                for (int jj = 0; jj < ND_; jj++)
                    v = fmaf(alph[lrow * 4 + jj], sF[jj * D_ + col + j], v);
                po[j] = v;
            }
            *(float4*)&x2[(size_t)row * D_ + col] = o;
        }
    }
}

// ---------------- glu_ln: LN1 in smem + GLU GEMM (split-K 512) ----------------
__global__ void __launch_bounds__(512) glu_ln(
    const float* __restrict__ x2, const float* __restrict__ g1, const float* __restrict__ b1,
    const float* __restrict__ W, const float* __restrict__ bias,
    const float* __restrict__ dw, const float* __restrict__ db,
    const float* __restrict__ bs, const float* __restrict__ bb, float* __restrict__ outp)
{
    extern __shared__ __align__(16) float sh[];
    float* Xs = sh;                        // [192][68]
    float* Wa = Xs + ASF_FLOATS;           // [192][64]; later redA
    float* Wg = Wa + WSF_FLOATS;           // [192][64]; later redG
    float* pm = Wg + WSF_FLOATS;           // [8][64]
    float* pv = pm + 512;
    float* rowm = pv + 512;
    float* rowr = rowm + 64;
    int blk = blockIdx.x;
    int m0 = (blk / 3) * 64, n0 = (blk % 3) * 64;
    int tid = threadIdx.x;
    int kh = tid >> 8, sub = tid & 255;

    skA(Xs, x2, D_, m0, D_);
    for (int idx = tid; idx < D_ * 16; idx += 512) {
        int k = idx >> 4, c4 = idx & 15;
        *(float4*)&Wa[k * 64 + c4 * 4] = *(const float4*)&W[(size_t)k * D2_ + n0 + c4 * 4];
        *(float4*)&Wg[k * 64 + c4 * 4] = *(const float4*)&W[(size_t)k * D2_ + D_ + n0 + c4 * 4];
    }
    __syncthreads();
    {
        int row = tid & 63, part = tid >> 6;   // 8 partials x 24 k each
        float s = 0.f, s2 = 0.f;
#pragma unroll 8
        for (int k = part * 24; k < part * 24 + 24; k++) {
            float v = Xs[k * AST + row]; s += v; s2 += v * v;
        }
        pm[part * 64 + row] = s; pv[part * 64 + row] = s2;
    }
    __syncthreads();
    if (tid < 64) {
        float ts = 0.f, ts2 = 0.f;
#pragma unroll
        for (int p = 0; p < 8; p++) { ts += pm[p * 64 + tid]; ts2 += pv[p * 64 + tid]; }
        float m = ts / D_;
        rowm[tid] = m;
        rowr[tid] = rsqrtf(ts2 / D_ - m * m + EPS_);
    }
    __syncthreads();
    for (int idx = tid; idx < D_ * 64; idx += 512) {
        int k = idx >> 6, r = idx & 63;
        Xs[k * AST + r] = (Xs[k * AST + r] - rowm[r]) * rowr[r] * g1[k] + b1[k];
    }
    __syncthreads();
    float cA[4][4] = {}, cG[4][4] = {};
    {
        int tx = sub & 15, ty = sub >> 4;
        const float* pa = Xs + kh * 96 * AST + ty * 4;
        const float* pba = Wa + kh * 96 * 64 + tx * 4;
        const float* pbg = Wg + kh * 96 * 64 + tx * 4;
#pragma unroll 8
        for (int kk = 0; kk < 96; kk++) {
            float4 af = *(const float4*)(pa + kk * AST);
            float4 ba = *(const float4*)(pba + kk * 64);
            float4 bg = *(const float4*)(pbg + kk * 64);
            float a4[4] = {af.x, af.y, af.z, af.w};
            float p4[4] = {ba.x, ba.y, ba.z, ba.w};
            float q4[4] = {bg.x, bg.y, bg.z, bg.w};
#pragma unroll
            for (int i = 0; i < 4; i++)
#pragma unroll
                for (int j = 0; j < 4; j++) {
                    cA[i][j] = fmaf(a4[i], p4[j], cA[i][j]);
                    cG[i][j] = fmaf(a4[i], q4[j], cG[i][j]);
                }
        }
    }
    skReduce(Wa, cA, kh, sub);
    skReduce(Wg, cG, kh, sub);
    if (kh == 0) {
        int tx = sub & 15, ty = sub >> 4;
#pragma unroll
        for (int i = 0; i < 4; i++) {
            int row = m0 + ty * 4 + i, col = n0 + tx * 4;
            float4 o; float* po = &o.x;
#pragma unroll
            for (int j = 0; j < 4; j++) {
                float a = cA[i][j] + bias[col + j];
                float g = cG[i][j] + bias[D_ + col + j];
                float h = a * (1.f / (1.f + expf(-g)));
                h = h * dw[col + j] + db[col + j];
                h = h * bs[col + j] + bb[col + j];
                h = h * (1.f / (1.f + expf(-h)));
                po[j] = h;
            }
            *(float4*)&outp[(size_t)row * D_ + col] = o;
        }
    }
}

// ---------------- pw2 GEMM (split-K 512, residual) ----------------
__global__ void __launch_bounds__(512) gemm_pw2(
    const float* __restrict__ A, const float* __restrict__ W,
    const float* __restrict__ bias, const float* __restrict__ res, float* __restrict__ C)
{
    extern __shared__ __align__(16) float sh[];
    float* Asf = sh;
    float* Wsf = sh + ASF_FLOATS;
    int blk = blockIdx.x;
    int m0 = (blk / 3) * 64, n0 = (blk % 3) * 64;
    int tid = threadIdx.x;
    int kh = tid >> 8, sub = tid & 255;
    skA(Asf, A, D_, m0, D_);
    skW(Wsf, W, D_, n0, D_, false);
    __syncthreads();
    float c[4][4] = {};
    skC<D_>(Asf, Wsf, c, kh, sub);
    skReduce(Wsf, c, kh, sub);
    if (kh == 0) {
        int tx = sub & 15, ty = sub >> 4;
#pragma unroll
        for (int i = 0; i < 4; i++) {
            int row = m0 + ty * 4 + i, col = n0 + tx * 4;
            float4 rv = *(const float4*)&res[(size_t)row * D_ + col];
            float4 o;
            o.x = c[i][0] + bias[col + 0] + rv.x;
            o.y = c[i][1] + bias[col + 1] + rv.y;
            o.z = c[i][2] + bias[col + 2] + rv.z;
            o.w = c[i][3] + bias[col + 3] + rv.w;
            *(float4*)&C[(size_t)row * D_ + col] = o;
        }
    }
}

// ---------------- rec_t ----------------
__global__ void __launch_bounds__(256) rec_t_kernel(
    float* __restrict__ ERR, const float* __restrict__ Kmat, const float* __restrict__ Vmat)
{
    __shared__ float sK[NT_][D_ + 1];
    __shared__ float Acf[NT_][NT_];
    __shared__ float cd[NT_];
    int b = blockIdx.x, tid = threadIdx.x;
    if (tid < NT_) cd[tid] = cdv(tid);
    for (int idx = tid; idx < NT_ * D_; idx += 256)
        sK[idx / D_][idx % D_] = Kmat[(size_t)b * NT_ * D_ + idx];
    __syncthreads();
    const int NP = NT_ * (NT_ - 1) / 2;
    for (int p = tid; p < NP; p += 256) {
        int i = (int)((1.0f + sqrtf(1.0f + 8.0f * (float)p)) * 0.5f);
        while (i * (i - 1) / 2 > p) i--;
        while ((i + 1) * i / 2 <= p) i++;
        int j = p - i * (i - 1) / 2;
        float s0 = 0.f, s1 = 0.f;
#pragma unroll 8
        for (int kk = 0; kk < D_; kk += 2) {
            s0 = fmaf(sK[j][kk],     sK[i][kk],     s0);
            s1 = fmaf(sK[j][kk + 1], sK[i][kk + 1], s1);
        }
        Acf[j][i] = cd[i - 1 - j] * (s0 + s1);
    }
    __syncthreads();
    if (tid < D_) {
        float err[NT_];
#pragma unroll
        for (int i = 0; i < NT_; i++) {
            float a0 = 0.f, a1 = 0.f;
#pragma unroll
            for (int j = 0; j < i; j++) {
                if (j & 1) a1 = fmaf(Acf[j][i], err[j], a1);
                else       a0 = fmaf(Acf[j][i], err[j], a0);
            }
            err[i] = Vmat[(size_t)(b * NT_ + i) * D_ + tid] - a0 - a1;
            ERR[(size_t)(b * NT_ + i) * D_ + tid] = err[i];
        }
    }
}

// ---------------- qkfinal ----------------
__global__ void __launch_bounds__(192) qkfinal(
    const float* __restrict__ x3, const float* __restrict__ Kt, const float* __restrict__ Et,
    const float* __restrict__ g2, const float* __restrict__ b2, float* __restrict__ pp)
{
    extern __shared__ __align__(16) float sh[];
    float (*sKT)[33] = (float (*)[33])sh;
    float* sEt = sh + 192 * 33;
    float* red = sEt + NT_ * D_;
    float* alpha = red + 192;
    float* cd = alpha + 32;
    float* lred = cd + 32;
    int blk = blockIdx.x;
    int b = blk >> 4, tc = blk & 15, t0 = tc * 16;
    int tid = threadIdx.x;
    if (tid < NT_) cd[tid] = cdv(tid);
    for (int idx = tid; idx < NT_ * D_; idx += 192) {
        int j = idx / D_, e = idx % D_;
        sKT[e][j] = Kt[(size_t)(b * NT_ + j) * D_ + e];
        sEt[idx] = Et[(size_t)b * NT_ * D_ + idx];
    }
    __syncthreads();
    int j = tid & 31, g = tid >> 5;
    float ps = 0.f;
    for (int tt = 0; tt < 16; tt++) {
        int t = t0 + tt, row = b * T_ + t, r = t >> 3;
        {
            const float* qr = x3 + (size_t)row * D_;
            float part = 0.f;
#pragma unroll
            for (int u = 0; u < 32; u++) part = fmaf(qr[g * 32 + u], sKT[g * 32 + u][j], part);
            red[j * 6 + g] = part;
        }
        __syncthreads();
        if (tid < NT_) {
            float s = 0.f;
#pragma unroll
            for (int gg = 0; gg < 6; gg++) s += red[tid * 6 + gg];
            alpha[tid] = (tid <= r) ? cd[r - tid] * s : 0.f;
        }
        __syncthreads();
        float s = 0.f;
        for (int jj = 0; jj <= r; jj++) s = fmaf(alpha[jj], sEt[jj * D_ + tid], s);
        float x4 = x3[(size_t)row * D_ + tid] + 0.5f * s;
        float sm = x4, s2 = x4 * x4;
#pragma unroll
        for (int o = 16; o > 0; o >>= 1) {
            sm += __shfl_xor_sync(~0u, sm, o);
            s2 += __shfl_xor_sync(~0u, s2, o);
        }
        if ((tid & 31) == 0) { lred[tid >> 5] = sm; lred[6 + (tid >> 5)] = s2; }
        __syncthreads();
        float ts = 0.f, ts2 = 0.f;
#pragma unroll
        for (int i = 0; i < 6; i++) { ts += lred[i]; ts2 += lred[6 + i]; }
        float m = ts / D_;
        float var = ts2 / D_ - m * m;
        ps += (x4 - m) * rsqrtf(var + EPS_) * g2[tid] + b2[tid];
        __syncthreads();
    }
    pp[(size_t)(b * 16 + tc) * D_ + tid] = ps;
}

// ---------------- pool + classifier ----------------
__global__ void __launch_bounds__(192) poolcls(
    const float* __restrict__ pp, const float* __restrict__ Wc,
    const float* __restrict__ bc, float* __restrict__ out)
{
    __shared__ float pooled[D_];
    int b = blockIdx.x, tid = threadIdx.x;
    float s = 0.f;
#pragma unroll
    for (int q = 0; q < 16; q++) s += pp[(size_t)(b * 16 + q) * D_ + tid];
    pooled[tid] = s * (1.f / T_);
    __syncthreads();
    if (tid < NC_) {
        float acc = bc[tid];
#pragma unroll 8
        for (int e = 0; e < D_; e++) acc = fmaf(pooled[e], Wc[e * NC_ + tid], acc);
        out[b * NC_ + tid] = acc;
    }
}

// =====================================================================
extern "C" void kernel_launch(void* const* d_in, const int* in_sizes, int n_in,
                              void* d_out, int out_size)
{
    const float* x     = (const float*)d_in[0];
    const float* W_in  = (const float*)d_in[1];
    const float* b_in  = (const float*)d_in[2];
    const float* Wv_a  = (const float*)d_in[3];
    const float* bv_a  = (const float*)d_in[4];
    const float* Wo_a  = (const float*)d_in[5];
    const float* bo_a  = (const float*)d_in[6];
    const float* ln1_g = (const float*)d_in[7];
    const float* ln1_b = (const float*)d_in[8];
    const float* pw1_w = (const float*)d_in[9];
    const float* pw1_b = (const float*)d_in[10];
    const float* dw_w  = (const float*)d_in[11];
    const float* dw_b  = (const float*)d_in[12];
    const float* bn_s  = (const float*)d_in[13];
    const float* bn_b  = (const float*)d_in[14];
    const float* pw2_w = (const float*)d_in[15];
    const float* pw2_b = (const float*)d_in[16];
    const float* Wk_t  = (const float*)d_in[17];
    const float* Wv_t  = (const float*)d_in[18];
    const float* Wq_t  = (const float*)d_in[19];
    const float* Wk_d  = (const float*)d_in[20];
    const float* Wv_d  = (const float*)d_in[21];
    const float* Wq_d  = (const float*)d_in[22];
    const float* ln2_g = (const float*)d_in[23];
    const float* ln2_b = (const float*)d_in[24];
    const float* Wc    = (const float*)d_in[25];
    const float* bc    = (const float*)d_in[26];
    float* out = (float*)d_out;

    float *xp, *x2, *g2p, *x3, *Kd, *Vd, *Qd, *Ed, *Fd, *Kt, *Vt, *Qt, *Et;
    float *Wao, *bao, *Wkqd, *Wkqt, *pp;
    cudaGetSymbolAddress((void**)&xp,   g_xp);
    cudaGetSymbolAddress((void**)&x2,   g_x2);
    cudaGetSymbolAddress((void**)&g2p,  g_g2);
    cudaGetSymbolAddress((void**)&x3,   g_x3);
    cudaGetSymbolAddress((void**)&Kd,   g_Kd);
    cudaGetSymbolAddress((void**)&Vd,   g_Vd);
    cudaGetSymbolAddress((void**)&Qd,   g_Qd);
    cudaGetSymbolAddress((void**)&Ed,   g_Ed);
    cudaGetSymbolAddress((void**)&Fd,   g_Fd);
    cudaGetSymbolAddress((void**)&Kt,   g_Kt);
    cudaGetSymbolAddress((void**)&Vt,   g_Vt);
    cudaGetSymbolAddress((void**)&Qt,   g_Qt);
    cudaGetSymbolAddress((void**)&Et,   g_Et);
    cudaGetSymbolAddress((void**)&Wao,  g_Wao);
    cudaGetSymbolAddress((void**)&bao,  g_bao);
    cudaGetSymbolAddress((void**)&Wkqd, g_Wkqd);
    cudaGetSymbolAddress((void**)&Wkqt, g_Wkqt);
    cudaGetSymbolAddress((void**)&pp,   g_pp);

    const int X2_SMEM  = GEMM_SMEM + (ND_ * D_ * 2 + 256) * 4;
    const int GLU_SMEM = (ASF_FLOATS + 2 * WSF_FLOATS + 512 + 512 + 64 + 64) * 4;
    const int QKF_SMEM = (192 * 33 + NT_ * D_ + 192 + 32 + 32 + 12) * 4;
    cudaFuncSetAttribute(k0_comb,  cudaFuncAttributeMaxDynamicSharedMemorySize, GEMM_SMEM);
    cudaFuncSetAttribute(x2_fused, cudaFuncAttributeMaxDynamicSharedMemorySize, X2_SMEM);
    cudaFuncSetAttribute(glu_ln,   cudaFuncAttributeMaxDynamicSharedMemorySize, GLU_SMEM);
    cudaFuncSetAttribute(gemm_pw2, cudaFuncAttributeMaxDynamicSharedMemorySize, GEMM_SMEM);
    cudaFuncSetAttribute(qkfinal,  cudaFuncAttributeMaxDynamicSharedMemorySize, QKF_SMEM);

    k0_comb<<<124, 512, GEMM_SMEM>>>(x, W_in, b_in, Wv_a, Wo_a, bv_a, bo_a,
                                     Wk_d, Wq_d, Wk_t, Wq_t);
    projKVQ<<<B_ * ND_, 192>>>(Kd, Vd, Qd, xp, Wk_d, Wv_d, Wkqd, ND_, 64);
    rec_d_kernel<<<B_, 256>>>(Ed, Fd, Kd, Vd, Wao);
    x2_fused<<<96, 512, X2_SMEM>>>(xp, Wao, bao, Qd, Fd, x2);
    glu_ln<<<96, 512, GLU_SMEM>>>(x2, ln1_g, ln1_b, pw1_w, pw1_b, dw_w, dw_b, bn_s, bn_b, g2p);
    gemm_pw2<<<96, 512, GEMM_SMEM>>>(g2p, pw2_w, pw2_b, x2, x3);
    projKVQ<<<B_ * NT_, 192>>>(Kt, Vt, Qt, x3, Wk_t, Wv_t, Wkqt, NT_, 8);
    rec_t_kernel<<<B_, 256>>>(Et, Kt, Vt);
    qkfinal<<<B_ * 16, 192, QKF_SMEM>>>(x3, Qt, Et, ln2_g, ln2_b, pp);
    poolcls<<<B_, 192>>>(pp, Wc, bc, out);
}